// round 1
// baseline (speedup 1.0000x reference)
#include <cuda_runtime.h>

#define B_SZ    2048
#define N_IN    512
#define T_STEPS 100
#define H1      512
#define H2      256
#define O_OUT   5
#define M_TOT   (B_SZ * T_STEPS)   // 204800

// Scratch (static device globals: allocation-free per harness rules)
__device__ float g_xt[(size_t)M_TOT * N_IN];   // x transposed to (B*T, N)
__device__ float g_h1[(size_t)M_TOT * H1];     // precomputed h1 for all t
__device__ float g_w2t[H1 * H2];               // W2 transposed to [k][j]

// ---------------------------------------------------------------------------
// Transpose x (B, N, T) -> xt (B*T, N):  xt[(b*T+t)*N + n] = x[(b*N+n)*T + t]
// ---------------------------------------------------------------------------
__global__ void transpose_x_kernel(const float* __restrict__ x,
                                   float* __restrict__ xt) {
    __shared__ float tile[32][33];
    int b  = blockIdx.z;
    int t0 = blockIdx.x * 32;
    int n0 = blockIdx.y * 32;
    int tx = threadIdx.x, ty = threadIdx.y;   // 32 x 8
#pragma unroll
    for (int i = 0; i < 4; i++) {
        int n = n0 + ty + i * 8;
        int t = t0 + tx;
        if (t < T_STEPS)
            tile[ty + i * 8][tx] = x[((size_t)b * N_IN + n) * T_STEPS + t];
    }
    __syncthreads();
#pragma unroll
    for (int i = 0; i < 4; i++) {
        int t = t0 + ty + i * 8;
        int n = n0 + tx;
        if (t < T_STEPS)
            xt[((size_t)b * T_STEPS + t) * N_IN + n] = tile[tx][ty + i * 8];
    }
}

// ---------------------------------------------------------------------------
// Transpose W2 (H2, H1) -> W2T (H1, H2):  w2t[k*H2 + j] = w2[j*H1 + k]
// ---------------------------------------------------------------------------
__global__ void transpose_w2_kernel(const float* __restrict__ w2,
                                    float* __restrict__ w2t) {
    __shared__ float tile[32][33];
    int k0 = blockIdx.x * 32;   // H1/32 = 16
    int j0 = blockIdx.y * 32;   // H2/32 = 8
    int tx = threadIdx.x, ty = threadIdx.y;
#pragma unroll
    for (int i = 0; i < 4; i++)
        tile[ty + i * 8][tx] = w2[(size_t)(j0 + ty + i * 8) * H1 + k0 + tx];
    __syncthreads();
#pragma unroll
    for (int i = 0; i < 4; i++)
        w2t[(size_t)(k0 + ty + i * 8) * H2 + j0 + tx] = tile[tx][ty + i * 8];
}

// ---------------------------------------------------------------------------
// GEMM1: C[m][j] = sum_k A[m][k] * W1[j][k] + b1[j]
// M = 204800, N = 512, K = 512.  128x128 block tile, 8x8 per-thread microtile.
// ---------------------------------------------------------------------------
__global__ __launch_bounds__(256) void gemm1_kernel(const float* __restrict__ A,
                                                    const float* __restrict__ W,
                                                    const float* __restrict__ bias,
                                                    float* __restrict__ C) {
    __shared__ float As[8][128];
    __shared__ float Bs[8][128];
    int m0  = blockIdx.x * 128;        // 1600 tiles, exact
    int j0  = blockIdx.y * 128;        // 4 tiles, exact
    int tid = threadIdx.x;
    int tx  = tid & 15, ty = tid >> 4;
    int lrow = tid >> 1;
    int lcol = (tid & 1) * 4;

    const float* Ap = A + (size_t)(m0 + lrow) * 512 + lcol;
    const float* Wp = W + (size_t)(j0 + lrow) * 512 + lcol;

    float acc[8][8];
#pragma unroll
    for (int i = 0; i < 8; i++)
#pragma unroll
        for (int j = 0; j < 8; j++) acc[i][j] = 0.0f;

    float4 av = *(const float4*)Ap;
    float4 wv = *(const float4*)Wp;

    for (int k0 = 0; k0 < 512; k0 += 8) {
        As[lcol + 0][lrow] = av.x; As[lcol + 1][lrow] = av.y;
        As[lcol + 2][lrow] = av.z; As[lcol + 3][lrow] = av.w;
        Bs[lcol + 0][lrow] = wv.x; Bs[lcol + 1][lrow] = wv.y;
        Bs[lcol + 2][lrow] = wv.z; Bs[lcol + 3][lrow] = wv.w;
        __syncthreads();
        if (k0 + 8 < 512) {
            av = *(const float4*)(Ap + k0 + 8);
            wv = *(const float4*)(Wp + k0 + 8);
        }
#pragma unroll
        for (int kk = 0; kk < 8; kk++) {
            float4 a0 = *(const float4*)&As[kk][ty * 8];
            float4 a1 = *(const float4*)&As[kk][ty * 8 + 4];
            float4 b0 = *(const float4*)&Bs[kk][tx * 8];
            float4 b1 = *(const float4*)&Bs[kk][tx * 8 + 4];
            float ar[8] = {a0.x, a0.y, a0.z, a0.w, a1.x, a1.y, a1.z, a1.w};
            float br[8] = {b0.x, b0.y, b0.z, b0.w, b1.x, b1.y, b1.z, b1.w};
#pragma unroll
            for (int i = 0; i < 8; i++)
#pragma unroll
                for (int j = 0; j < 8; j++)
                    acc[i][j] = fmaf(ar[i], br[j], acc[i][j]);
        }
        __syncthreads();
    }

    float4 bs0 = *(const float4*)&bias[j0 + tx * 8];
    float4 bs1 = *(const float4*)&bias[j0 + tx * 8 + 4];
    float bb[8] = {bs0.x, bs0.y, bs0.z, bs0.w, bs1.x, bs1.y, bs1.z, bs1.w};
#pragma unroll
    for (int i = 0; i < 8; i++) {
        float* cp = C + (size_t)(m0 + ty * 8 + i) * 512 + j0 + tx * 8;
        float4 o0 = make_float4(acc[i][0] + bb[0], acc[i][1] + bb[1],
                                acc[i][2] + bb[2], acc[i][3] + bb[3]);
        float4 o1 = make_float4(acc[i][4] + bb[4], acc[i][5] + bb[5],
                                acc[i][6] + bb[6], acc[i][7] + bb[7]);
        *(float4*)cp = o0;
        *(float4*)(cp + 4) = o1;
    }
}

// ---------------------------------------------------------------------------
// Phase B: persistent, row-parallel. 128 blocks x 16 batch rows, 256 threads.
// All membrane state lives in registers/SMEM for the whole T loop.
// ---------------------------------------------------------------------------
#define RB 16
#define PHASEB_SMEM ((RB * 512 + RB * 256 + O_OUT * 256 + 8 + RB * O_OUT * 2) * 4)

__global__ __launch_bounds__(256) void phase_b_kernel(
    const float* __restrict__ h1all, const float* __restrict__ w2t,
    const float* __restrict__ b2,    const float* __restrict__ Wo,
    const float* __restrict__ bo,    float* __restrict__ out) {
    extern __shared__ float sm[];
    float* s1  = sm;                    // [RB][512]
    float* s2  = s1 + RB * 512;         // [RB][256]
    float* Wos = s2 + RB * 256;         // [5][256]
    float* bos = Wos + O_OUT * 256;     // [5] (+pad)
    float* vo  = bos + 8;               // [RB][5]
    float* oac = vo + RB * O_OUT;       // [RB][5]

    int tid = threadIdx.x;
    int b0  = blockIdx.x * RB;

    for (int i = tid; i < O_OUT * 256; i += 256) Wos[i] = Wo[i];
    if (tid < O_OUT) bos[tid] = bo[tid];
    if (tid < RB * O_OUT) { vo[tid] = 0.0f; oac[tid] = 0.0f; }

    float v1r[32];                      // LIF1 state: idx = i*256 + tid
#pragma unroll
    for (int i = 0; i < 32; i++) v1r[i] = 0.0f;
    float v2r[RB];                      // LIF2 state: column j = tid, rows r
#pragma unroll
    for (int r = 0; r < RB; r++) v2r[r] = 0.0f;
    float b2r = b2[tid];
    int wrp = tid >> 5, lane = tid & 31;
    __syncthreads();

#pragma unroll 1
    for (int t = 0; t < T_STEPS; t++) {
        // ---- LIF1 (inputs precomputed in g_h1) ----
#pragma unroll
        for (int i = 0; i < 32; i++) {
            int idx = i * 256 + tid;
            int r = idx >> 9, k = idx & 511;
            float h = h1all[((size_t)(b0 + r) * T_STEPS + t) * H1 + k];
            float v = v1r[i];
            v = v + (h - v) * 0.5f;
            float s = (v >= 1.0f) ? 1.0f : 0.0f;
            v1r[i] = v * (1.0f - s);
            s1[r * 512 + k] = s;
        }
        __syncthreads();

        // ---- GEMM2 + LIF2: thread owns output column j = tid, all RB rows ----
        float acc2[RB];
#pragma unroll
        for (int r = 0; r < RB; r++) acc2[r] = b2r;
        float wc[4];
#pragma unroll
        for (int c = 0; c < 4; c++) wc[c] = w2t[c * H2 + tid];
#pragma unroll 2
        for (int k0 = 0; k0 < 512; k0 += 4) {
            float wn[4];
            if (k0 + 4 < 512) {
#pragma unroll
                for (int c = 0; c < 4; c++) wn[c] = w2t[(k0 + 4 + c) * H2 + tid];
            }
#pragma unroll
            for (int r = 0; r < RB; r++) {
                float4 s4 = *(const float4*)&s1[r * 512 + k0];
                float a = acc2[r];
                a = fmaf(s4.x, wc[0], a);
                a = fmaf(s4.y, wc[1], a);
                a = fmaf(s4.z, wc[2], a);
                a = fmaf(s4.w, wc[3], a);
                acc2[r] = a;
            }
#pragma unroll
            for (int c = 0; c < 4; c++) wc[c] = wn[c];
        }
#pragma unroll
        for (int r = 0; r < RB; r++) {
            float v = v2r[r];
            v = v + (acc2[r] - v) * 0.5f;
            float s = (v >= 1.0f) ? 1.0f : 0.0f;
            v2r[r] = v * (1.0f - s);
            s2[r * 256 + tid] = s;
        }
        __syncthreads();

        // ---- GEMM3 + LIF3: 80 (r,c) pairs, 10 per warp, warp-reduce over j ----
#pragma unroll
        for (int pp = 0; pp < 10; pp++) {
            int p = wrp * 10 + pp;   // 0..79 exactly
            int r = p / O_OUT, c = p % O_OUT;
            float sum = 0.0f;
#pragma unroll
            for (int jj = 0; jj < 8; jj++) {
                int j = lane + jj * 32;
                sum = fmaf(s2[r * 256 + j], Wos[c * 256 + j], sum);
            }
#pragma unroll
            for (int off = 16; off > 0; off >>= 1)
                sum += __shfl_xor_sync(0xffffffffu, sum, off);
            if (lane == 0) {
                float o = sum + bos[c];
                float v = vo[r * O_OUT + c];
                v = v + (o - v) * 0.5f;
                float s = (v >= 1.0f) ? 1.0f : 0.0f;
                vo[r * O_OUT + c] = v * (1.0f - s);
                oac[r * O_OUT + c] += s;
            }
        }
        __syncthreads();
    }

    if (tid < RB * O_OUT) {
        int r = tid / O_OUT, c = tid % O_OUT;
        out[(size_t)(b0 + r) * O_OUT + c] = oac[tid] / 100.0f;
    }
}

// ---------------------------------------------------------------------------
extern "C" void kernel_launch(void* const* d_in, const int* in_sizes, int n_in,
                              void* d_out, int out_size) {
    const float* x  = (const float*)d_in[0];
    const float* W1 = (const float*)d_in[1];
    const float* b1 = (const float*)d_in[2];
    const float* W2 = (const float*)d_in[3];
    const float* b2 = (const float*)d_in[4];
    const float* Wo = (const float*)d_in[5];
    const float* bo = (const float*)d_in[6];
    float* out = (float*)d_out;

    float *xt, *h1, *w2t;
    cudaGetSymbolAddress((void**)&xt,  g_xt);
    cudaGetSymbolAddress((void**)&h1,  g_h1);
    cudaGetSymbolAddress((void**)&w2t, g_w2t);

    cudaFuncSetAttribute(phase_b_kernel,
                         cudaFuncAttributeMaxDynamicSharedMemorySize, PHASEB_SMEM);

    transpose_x_kernel<<<dim3(4, 16, B_SZ), dim3(32, 8)>>>(x, xt);
    transpose_w2_kernel<<<dim3(16, 8), dim3(32, 8)>>>(W2, w2t);
    gemm1_kernel<<<dim3(M_TOT / 128, H1 / 128), 256>>>(xt, W1, b1, h1);
    phase_b_kernel<<<B_SZ / RB, 256, PHASEB_SMEM>>>(h1, w2t, b2, Wo, bo, out);
}

// round 5
// speedup vs baseline: 3.0233x; 3.0233x over previous
#include <cuda_runtime.h>
#include <cuda_fp16.h>
#include <cstdint>

#define B_SZ    2048
#define N_IN    512
#define T_STEPS 100
#define H1      512
#define H2      256
#define O_OUT   5
#define M_TOT   (B_SZ * T_STEPS)   // 204800

// ---------------- scratch globals (allocation-free rule) ----------------
__device__ __half g_xh[(size_t)M_TOT * N_IN];   // x transposed, hi split
__device__ __half g_xl[(size_t)M_TOT * N_IN];   // x transposed, lo split
__device__ __half g_w1h[H1 * N_IN];
__device__ __half g_w1l[H1 * N_IN];
__device__ float  g_h1[(size_t)M_TOT * H1];     // fp32 h1 for all t
__device__ float  g_w2t[H1 * H2];               // W2 transposed [k][j]

// ---------------- PTX helpers ----------------
__device__ __forceinline__ uint32_t smem_u32(const void* p) {
    uint32_t a;
    asm("{ .reg .u64 t; cvta.to.shared.u64 t, %1; cvt.u32.u64 %0, t; }"
        : "=r"(a) : "l"(p));
    return a;
}
__device__ __forceinline__ void cp_async16(uint32_t dst, const void* src) {
    asm volatile("cp.async.cg.shared.global [%0], [%1], 16;" :: "r"(dst), "l"(src));
}
#define CP_COMMIT() asm volatile("cp.async.commit_group;" ::: "memory")
template <int N>
__device__ __forceinline__ void cp_wait() {
    asm volatile("cp.async.wait_group %0;" :: "n"(N) : "memory");
}
__device__ __forceinline__ void ldsm4(uint32_t* r, uint32_t addr) {
    asm volatile("ldmatrix.sync.aligned.m8n8.x4.shared.b16 {%0,%1,%2,%3}, [%4];"
                 : "=r"(r[0]), "=r"(r[1]), "=r"(r[2]), "=r"(r[3]) : "r"(addr));
}
__device__ __forceinline__ void ldsm4t(uint32_t* r, uint32_t addr) {
    asm volatile("ldmatrix.sync.aligned.m8n8.x4.trans.shared.b16 {%0,%1,%2,%3}, [%4];"
                 : "=r"(r[0]), "=r"(r[1]), "=r"(r[2]), "=r"(r[3]) : "r"(addr));
}
__device__ __forceinline__ void mma16816(float* c, const uint32_t* a, const uint32_t* b) {
    asm volatile("mma.sync.aligned.m16n8k16.row.col.f32.f16.f16.f32 "
                 "{%0,%1,%2,%3},{%4,%5,%6,%7},{%8,%9},{%0,%1,%2,%3};"
                 : "+f"(c[0]), "+f"(c[1]), "+f"(c[2]), "+f"(c[3])
                 : "r"(a[0]), "r"(a[1]), "r"(a[2]), "r"(a[3]), "r"(b[0]), "r"(b[1]));
}

// ---------------------------------------------------------------------------
// Transpose + fp16-split x: (B, N, T) -> xh/xl at [(b*T+t)][n]
// ---------------------------------------------------------------------------
__global__ void transpose_split_x(const float* __restrict__ x,
                                  __half* __restrict__ xh,
                                  __half* __restrict__ xl) {
    __shared__ float tile[32][33];
    int b  = blockIdx.z;
    int t0 = blockIdx.x * 32;
    int n0 = blockIdx.y * 32;
    int tx = threadIdx.x, ty = threadIdx.y;   // 32 x 8
#pragma unroll
    for (int i = 0; i < 4; i++) {
        int n = n0 + ty + i * 8;
        int t = t0 + tx;
        if (t < T_STEPS)
            tile[ty + i * 8][tx] = x[((size_t)b * N_IN + n) * T_STEPS + t];
    }
    __syncthreads();
#pragma unroll
    for (int i = 0; i < 4; i++) {
        int t = t0 + ty + i * 8;
        int n = n0 + tx;
        if (t < T_STEPS) {
            float v = tile[tx][ty + i * 8];
            __half hi = __float2half_rn(v);
            __half lo = __float2half_rn(v - __half2float(hi));
            size_t o = ((size_t)b * T_STEPS + t) * N_IN + n;
            xh[o] = hi; xl[o] = lo;
        }
    }
}

// ---------------------------------------------------------------------------
// Split W1 into fp16 hi/lo
// ---------------------------------------------------------------------------
__global__ void split_w1(const float* __restrict__ w,
                         __half* __restrict__ wh,
                         __half* __restrict__ wl) {
    int i = blockIdx.x * 256 + threadIdx.x;
    float v = w[i];
    __half hi = __float2half_rn(v);
    __half lo = __float2half_rn(v - __half2float(hi));
    wh[i] = hi; wl[i] = lo;
}

// ---------------------------------------------------------------------------
// Transpose W2 (H2, H1) -> (H1, H2)
// ---------------------------------------------------------------------------
__global__ void transpose_w2_kernel(const float* __restrict__ w2,
                                    float* __restrict__ w2t) {
    __shared__ float tile[32][33];
    int k0 = blockIdx.x * 32;
    int j0 = blockIdx.y * 32;
    int tx = threadIdx.x, ty = threadIdx.y;
#pragma unroll
    for (int i = 0; i < 4; i++)
        tile[ty + i * 8][tx] = w2[(size_t)(j0 + ty + i * 8) * H1 + k0 + tx];
    __syncthreads();
#pragma unroll
    for (int i = 0; i < 4; i++)
        w2t[(size_t)(k0 + ty + i * 8) * H2 + j0 + tx] = tile[tx][ty + i * 8];
}

// ---------------------------------------------------------------------------
// GEMM1 via mma.sync fp16 (2-way split, 3 passes):
//   h1[m][j] = sum_k x[m][k] * W1[j][k] + b1[j]
// BM=128, BN=128, BK=32, 3-stage cp.async pipeline, 8 warps (4m x 2n).
// Smem rows padded: 32 halves data + 8 pad = 40 halves = 80B stride.
// ---------------------------------------------------------------------------
#define BK        32
#define NKC       (N_IN / BK)        // 16
#define ROWB      80                 // bytes per padded smem row
#define MATB      (128 * ROWB)       // 10240 bytes per matrix tile
#define STAGEB    (4 * MATB)         // Ah, Al, Wh, Wl
#define GEMM_SMEM (3 * STAGEB)       // 3 stages = 122880

__device__ __forceinline__ void g1_load_stage(uint32_t sbase, int kc,
                                              const __half* xh, const __half* xl,
                                              const __half* wh, const __half* wl,
                                              int m0, int j0, int tid) {
    int kb = kc * BK;
#pragma unroll
    for (int i = 0; i < 2; i++) {
        int c = tid + i * 256;              // 0..511
        int row = c >> 2, seg = c & 3;
        uint32_t d = (uint32_t)(row * ROWB + seg * 16);
        const size_t ga = (size_t)(m0 + row) * N_IN + kb + seg * 8;
        const size_t gw = (size_t)(j0 + row) * N_IN + kb + seg * 8;
        cp_async16(sbase + d,             xh + ga);
        cp_async16(sbase + MATB + d,      xl + ga);
        cp_async16(sbase + 2 * MATB + d,  wh + gw);
        cp_async16(sbase + 3 * MATB + d,  wl + gw);
    }
    CP_COMMIT();
}

__global__ __launch_bounds__(256, 1) void gemm1_mma_kernel(
    const __half* __restrict__ xh, const __half* __restrict__ xl,
    const __half* __restrict__ wh, const __half* __restrict__ wl,
    const float* __restrict__ b1, float* __restrict__ h1) {
    extern __shared__ char smem[];
    uint32_t sb = smem_u32(smem);
    int tid  = threadIdx.x;
    int wid  = tid >> 5, lane = tid & 31;
    int m0   = blockIdx.y * 128;
    int j0   = blockIdx.x * 128;
    int mbase = (wid & 3) * 32;          // warp m offset
    int nbase = (wid >> 2) * 64;         // warp n offset
    int grp  = lane >> 3, lrow = lane & 7;

    // ldmatrix per-lane base offsets (within a matrix tile)
    uint32_t aoff = (uint32_t)((mbase + (grp & 1) * 8 + lrow) * ROWB + (grp >> 1) * 16);
    uint32_t boff = (uint32_t)((nbase + (grp >> 1) * 8 + lrow) * ROWB + (grp & 1) * 16);

    float acc[2][8][4];
#pragma unroll
    for (int mt = 0; mt < 2; mt++)
#pragma unroll
        for (int nt = 0; nt < 8; nt++)
#pragma unroll
            for (int q = 0; q < 4; q++) acc[mt][nt][q] = 0.0f;

    // prologue: stages 0, 1
    g1_load_stage(sb,          0, xh, xl, wh, wl, m0, j0, tid);
    g1_load_stage(sb + STAGEB, 1, xh, xl, wh, wl, m0, j0, tid);

#pragma unroll 1
    for (int kc = 0; kc < NKC; kc++) {
        __syncthreads();   // all warps done with buffer (kc+2)%3's old data
        if (kc + 2 < NKC)
            g1_load_stage(sb + ((kc + 2) % 3) * STAGEB, kc + 2,
                          xh, xl, wh, wl, m0, j0, tid);
        else
            CP_COMMIT();
        cp_wait<2>();      // stage kc has arrived
        __syncthreads();

        uint32_t sA  = sb + (kc % 3) * STAGEB;
        uint32_t sAl = sA + MATB, sWh = sA + 2 * MATB, sWl = sA + 3 * MATB;
#pragma unroll
        for (int kk = 0; kk < 2; kk++) {
            uint32_t ah[2][4], al[2][4];
#pragma unroll
            for (int mt = 0; mt < 2; mt++) {
                ldsm4(ah[mt], sA  + aoff + mt * (16 * ROWB) + kk * 32);
                ldsm4(al[mt], sAl + aoff + mt * (16 * ROWB) + kk * 32);
            }
            uint32_t bh[8][2], bl[8][2];
#pragma unroll
            for (int nt2 = 0; nt2 < 4; nt2++) {
                uint32_t r[4];
                ldsm4t(r, sWh + boff + nt2 * (16 * ROWB) + kk * 32);
                bh[nt2 * 2][0] = r[0]; bh[nt2 * 2][1] = r[1];
                bh[nt2 * 2 + 1][0] = r[2]; bh[nt2 * 2 + 1][1] = r[3];
                ldsm4t(r, sWl + boff + nt2 * (16 * ROWB) + kk * 32);
                bl[nt2 * 2][0] = r[0]; bl[nt2 * 2][1] = r[1];
                bl[nt2 * 2 + 1][0] = r[2]; bl[nt2 * 2 + 1][1] = r[3];
            }
#pragma unroll
            for (int mt = 0; mt < 2; mt++)
#pragma unroll
                for (int nt = 0; nt < 8; nt++) {
                    mma16816(acc[mt][nt], ah[mt], bh[nt]);
                    mma16816(acc[mt][nt], ah[mt], bl[nt]);
                    mma16816(acc[mt][nt], al[mt], bh[nt]);
                }
        }
    }

    // epilogue: add bias, store fp32
    int r0 = lane >> 2, c0 = (lane & 3) * 2;
#pragma unroll
    for (int nt = 0; nt < 8; nt++) {
        int col = j0 + nbase + nt * 8 + c0;
        float2 bb = *(const float2*)&b1[col];
#pragma unroll
        for (int mt = 0; mt < 2; mt++) {
            int row = m0 + mbase + mt * 16 + r0;
            float2 v0 = make_float2(acc[mt][nt][0] + bb.x, acc[mt][nt][1] + bb.y);
            float2 v1 = make_float2(acc[mt][nt][2] + bb.x, acc[mt][nt][3] + bb.y);
            *(float2*)&h1[(size_t)row * H1 + col]       = v0;
            *(float2*)&h1[(size_t)(row + 8) * H1 + col] = v1;
        }
    }
}

// ---------------------------------------------------------------------------
// Phase B: deterministic spike-sparse LIF stack.
// RB=8 rows/block (warp w owns row w for LIF1/LIF3), 256 blocks.
// Sparse sums are bitwise-identical to dense ascending-k sums (adding 0.0
// is exact identity), so this matches round-1's rel_err=0.0 path.
// ---------------------------------------------------------------------------
#define RB 8
__global__ __launch_bounds__(256) void phase_b_kernel(
    const float* __restrict__ h1all, const float* __restrict__ w2t,
    const float* __restrict__ b2,    const float* __restrict__ Wo,
    const float* __restrict__ bo,    float* __restrict__ out) {
    __shared__ short    idx1[RB][512];
    __shared__ int      cnt1[RB];
    __shared__ uint32_t s2bits[RB][8];
    __shared__ float    Wos[O_OUT * 256];
    __shared__ float    bos[8];

    int tid  = threadIdx.x;
    int wid  = tid >> 5, lane = tid & 31;
    int b0   = blockIdx.x * RB;

    for (int i = tid; i < O_OUT * 256; i += 256) Wos[i] = Wo[i];
    if (tid < O_OUT) bos[tid] = bo[tid];

    float v1[16];                       // LIF1: warp wid owns row wid, k=i*32+lane
#pragma unroll
    for (int i = 0; i < 16; i++) v1[i] = 0.0f;
    float v2[RB];                       // LIF2: thread owns col j=tid, all rows
#pragma unroll
    for (int r = 0; r < RB; r++) v2[r] = 0.0f;
    float b2r = b2[tid];
    float vo = 0.0f, oac = 0.0f;        // LIF3: warp wid = row, lanes 0..4 = cols
    __syncthreads();

#pragma unroll 1
    for (int t = 0; t < T_STEPS; t++) {
        // ---- LIF1 + deterministic fired-list (ballot compaction, asc k) ----
        const float* hrow = h1all + ((size_t)(b0 + wid) * T_STEPS + t) * H1;
        int base = 0;
#pragma unroll
        for (int i = 0; i < 16; i++) {
            float h = hrow[i * 32 + lane];
            float v = v1[i];
            v = v + (h - v) * 0.5f;
            bool sp = (v >= 1.0f);
            v1[i] = sp ? 0.0f : v;
            uint32_t m = __ballot_sync(0xffffffffu, sp);
            if (sp)
                idx1[wid][base + __popc(m & ((1u << lane) - 1u))] = (short)(i * 32 + lane);
            base += __popc(m);
        }
        if (lane == 0) cnt1[wid] = base;
        __syncthreads();

        // ---- sparse GEMM2 + LIF2 (thread = col j = tid) ----
#pragma unroll
        for (int r = 0; r < RB; r++) {
            float acc = b2r;
            int n = cnt1[r];
            for (int i = 0; i < n; i++)
                acc += w2t[(size_t)idx1[r][i] * H2 + tid];
            float v = v2[r];
            v = v + (acc - v) * 0.5f;
            bool sp = (v >= 1.0f);
            v2[r] = sp ? 0.0f : v;
            uint32_t m = __ballot_sync(0xffffffffu, sp);
            if (lane == (r & 31)) s2bits[r][wid] = m;
        }
        __syncthreads();

        // ---- sparse GEMM3 + LIF3 (warp wid = row, lanes 0..4 = outputs) ----
        if (lane < O_OUT) {
            float sum = bos[lane];
#pragma unroll
            for (int w = 0; w < 8; w++) {
                uint32_t word = s2bits[wid][w];
                while (word) {
                    int j = w * 32 + (__ffs(word) - 1);
                    word &= word - 1;
                    sum += Wos[lane * 256 + j];
                }
            }
            float v = vo;
            v = v + (sum - v) * 0.5f;
            bool sp = (v >= 1.0f);
            vo = sp ? 0.0f : v;
            if (sp) oac += 1.0f;
        }
        __syncthreads();   // lists/bits stable until here; next t overwrites
    }

    if (lane < O_OUT)
        out[(size_t)(b0 + wid) * O_OUT + lane] = oac * (1.0f / T_STEPS);
}

// ---------------------------------------------------------------------------
extern "C" void kernel_launch(void* const* d_in, const int* in_sizes, int n_in,
                              void* d_out, int out_size) {
    const float* x  = (const float*)d_in[0];
    const float* W1 = (const float*)d_in[1];
    const float* b1 = (const float*)d_in[2];
    const float* W2 = (const float*)d_in[3];
    const float* b2 = (const float*)d_in[4];
    const float* Wo = (const float*)d_in[5];
    const float* bo = (const float*)d_in[6];
    float* out = (float*)d_out;

    __half *xh, *xl, *wh, *wl;
    float *h1, *w2t;
    cudaGetSymbolAddress((void**)&xh,  g_xh);
    cudaGetSymbolAddress((void**)&xl,  g_xl);
    cudaGetSymbolAddress((void**)&wh,  g_w1h);
    cudaGetSymbolAddress((void**)&wl,  g_w1l);
    cudaGetSymbolAddress((void**)&h1,  g_h1);
    cudaGetSymbolAddress((void**)&w2t, g_w2t);

    cudaFuncSetAttribute(gemm1_mma_kernel,
                         cudaFuncAttributeMaxDynamicSharedMemorySize, GEMM_SMEM);

    transpose_split_x<<<dim3(4, 16, B_SZ), dim3(32, 8)>>>(x, xh, xl);
    split_w1<<<(H1 * N_IN) / 256, 256>>>(W1, wh, wl);
    transpose_w2_kernel<<<dim3(16, 8), dim3(32, 8)>>>(W2, w2t);
    gemm1_mma_kernel<<<dim3(H1 / 128, M_TOT / 128), 256, GEMM_SMEM>>>(
        xh, xl, wh, wl, b1, h1);
    phase_b_kernel<<<B_SZ / RB, 256>>>(h1, w2t, b2, Wo, bo, out);
}

// round 6
// speedup vs baseline: 6.6407x; 2.1965x over previous
#include <cuda_runtime.h>
#include <cuda_fp16.h>
#include <cstdint>

#define B_SZ    2048
#define N_IN    512
#define T_STEPS 100
#define H1      512
#define H2      256
#define O_OUT   5
#define M_TOT   (B_SZ * T_STEPS)   // 204800

// ---------------- scratch globals (allocation-free rule) ----------------
__device__ __half g_xh[(size_t)M_TOT * N_IN];   // x transposed, fp16
__device__ __half g_w1h[H1 * N_IN];             // W1 hi split
__device__ __half g_w1l[H1 * N_IN];             // W1 lo split
__device__ float  g_h1[(size_t)M_TOT * H1];     // fp32 h1 for all t
__device__ float  g_w2t[H1 * H2];               // W2 transposed [k][j]

// ---------------- PTX helpers ----------------
__device__ __forceinline__ uint32_t smem_u32(const void* p) {
    uint32_t a;
    asm("{ .reg .u64 t; cvta.to.shared.u64 t, %1; cvt.u32.u64 %0, t; }"
        : "=r"(a) : "l"(p));
    return a;
}
__device__ __forceinline__ void cp_async16(uint32_t dst, const void* src) {
    asm volatile("cp.async.cg.shared.global [%0], [%1], 16;" :: "r"(dst), "l"(src));
}
#define CP_COMMIT() asm volatile("cp.async.commit_group;" ::: "memory")
template <int N>
__device__ __forceinline__ void cp_wait() {
    asm volatile("cp.async.wait_group %0;" :: "n"(N) : "memory");
}
__device__ __forceinline__ void ldsm4(uint32_t* r, uint32_t addr) {
    asm volatile("ldmatrix.sync.aligned.m8n8.x4.shared.b16 {%0,%1,%2,%3}, [%4];"
                 : "=r"(r[0]), "=r"(r[1]), "=r"(r[2]), "=r"(r[3]) : "r"(addr));
}
__device__ __forceinline__ void ldsm4t(uint32_t* r, uint32_t addr) {
    asm volatile("ldmatrix.sync.aligned.m8n8.x4.trans.shared.b16 {%0,%1,%2,%3}, [%4];"
                 : "=r"(r[0]), "=r"(r[1]), "=r"(r[2]), "=r"(r[3]) : "r"(addr));
}
__device__ __forceinline__ void mma16816(float* c, const uint32_t* a, const uint32_t* b) {
    asm volatile("mma.sync.aligned.m16n8k16.row.col.f32.f16.f16.f32 "
                 "{%0,%1,%2,%3},{%4,%5,%6,%7},{%8,%9},{%0,%1,%2,%3};"
                 : "+f"(c[0]), "+f"(c[1]), "+f"(c[2]), "+f"(c[3])
                 : "r"(a[0]), "r"(a[1]), "r"(a[2]), "r"(a[3]), "r"(b[0]), "r"(b[1]));
}

// ---------------------------------------------------------------------------
// Transpose x (B, N, T) -> fp16 xh at [(b*T+t)][n]
// ---------------------------------------------------------------------------
__global__ void transpose_half_x(const float* __restrict__ x,
                                 __half* __restrict__ xh) {
    __shared__ float tile[32][33];
    int b  = blockIdx.z;
    int t0 = blockIdx.x * 32;
    int n0 = blockIdx.y * 32;
    int tx = threadIdx.x, ty = threadIdx.y;   // 32 x 8
#pragma unroll
    for (int i = 0; i < 4; i++) {
        int n = n0 + ty + i * 8;
        int t = t0 + tx;
        if (t < T_STEPS)
            tile[ty + i * 8][tx] = x[((size_t)b * N_IN + n) * T_STEPS + t];
    }
    __syncthreads();
#pragma unroll
    for (int i = 0; i < 4; i++) {
        int t = t0 + ty + i * 8;
        int n = n0 + tx;
        if (t < T_STEPS)
            xh[((size_t)b * T_STEPS + t) * N_IN + n] =
                __float2half_rn(tile[tx][ty + i * 8]);
    }
}

// ---------------------------------------------------------------------------
// Split W1 into fp16 hi/lo
// ---------------------------------------------------------------------------
__global__ void split_w1(const float* __restrict__ w,
                         __half* __restrict__ wh,
                         __half* __restrict__ wl) {
    int i = blockIdx.x * 256 + threadIdx.x;
    float v = w[i];
    __half hi = __float2half_rn(v);
    __half lo = __float2half_rn(v - __half2float(hi));
    wh[i] = hi; wl[i] = lo;
}

// ---------------------------------------------------------------------------
// Transpose W2 (H2, H1) -> (H1, H2)
// ---------------------------------------------------------------------------
__global__ void transpose_w2_kernel(const float* __restrict__ w2,
                                    float* __restrict__ w2t) {
    __shared__ float tile[32][33];
    int k0 = blockIdx.x * 32;
    int j0 = blockIdx.y * 32;
    int tx = threadIdx.x, ty = threadIdx.y;
#pragma unroll
    for (int i = 0; i < 4; i++)
        tile[ty + i * 8][tx] = w2[(size_t)(j0 + ty + i * 8) * H1 + k0 + tx];
    __syncthreads();
#pragma unroll
    for (int i = 0; i < 4; i++)
        w2t[(size_t)(k0 + ty + i * 8) * H2 + j0 + tx] = tile[tx][ty + i * 8];
}

// ---------------------------------------------------------------------------
// GEMM1 via mma.sync fp16, 2 passes (xh*wh + xh*wl):
//   h1[m][j] = sum_k x[m][k] * W1[j][k] + b1[j]
// BM=128, BN=128, BK=32, 2-stage cp.async pipeline, 2 CTAs/SM.
// Warp grid 2(m) x 4(n): per-warp 64x32 tile.
// ---------------------------------------------------------------------------
#define BK        32
#define NKC       (N_IN / BK)        // 16
#define ROWB      80                 // bytes per padded smem row (32h + 8h pad)
#define MATB      (128 * ROWB)       // 10240 bytes per matrix tile
#define STAGEB    (3 * MATB)         // Ah, Wh, Wl = 30720
#define GEMM_SMEM (2 * STAGEB)       // 61440

__device__ __forceinline__ void g1_load_stage(uint32_t sbase, int kc,
                                              const __half* xh,
                                              const __half* wh, const __half* wl,
                                              int m0, int j0, int tid) {
    int kb = kc * BK;
#pragma unroll
    for (int i = 0; i < 2; i++) {
        int c = tid + i * 256;              // 0..511
        int row = c >> 2, seg = c & 3;
        uint32_t d = (uint32_t)(row * ROWB + seg * 16);
        const size_t ga = (size_t)(m0 + row) * N_IN + kb + seg * 8;
        const size_t gw = (size_t)(j0 + row) * N_IN + kb + seg * 8;
        cp_async16(sbase + d,             xh + ga);
        cp_async16(sbase + MATB + d,      wh + gw);
        cp_async16(sbase + 2 * MATB + d,  wl + gw);
    }
    CP_COMMIT();
}

__global__ __launch_bounds__(256, 2) void gemm1_mma_kernel(
    const __half* __restrict__ xh,
    const __half* __restrict__ wh, const __half* __restrict__ wl,
    const float* __restrict__ b1, float* __restrict__ h1) {
    extern __shared__ char smem[];
    uint32_t sb = smem_u32(smem);
    int tid  = threadIdx.x;
    int wid  = tid >> 5, lane = tid & 31;
    int m0   = blockIdx.y * 128;
    int j0   = blockIdx.x * 128;
    int mbase = (wid & 1) * 64;          // 2 m-groups, warp tile 64 rows
    int nbase = (wid >> 1) * 32;         // 4 n-groups, warp tile 32 cols
    int grp  = lane >> 3, lrow = lane & 7;

    // ldmatrix per-lane base offsets (within a matrix tile)
    uint32_t aoff = (uint32_t)((mbase + (grp & 1) * 8 + lrow) * ROWB + (grp >> 1) * 16);
    uint32_t boff = (uint32_t)((nbase + (grp >> 1) * 8 + lrow) * ROWB + (grp & 1) * 16);

    float acc[4][4][4];
#pragma unroll
    for (int mt = 0; mt < 4; mt++)
#pragma unroll
        for (int nt = 0; nt < 4; nt++)
#pragma unroll
            for (int q = 0; q < 4; q++) acc[mt][nt][q] = 0.0f;

    // prologue: stage 0
    g1_load_stage(sb, 0, xh, wh, wl, m0, j0, tid);

#pragma unroll 1
    for (int kc = 0; kc < NKC; kc++) {
        if (kc + 1 < NKC)
            g1_load_stage(sb + ((kc + 1) & 1) * STAGEB, kc + 1,
                          xh, wh, wl, m0, j0, tid);
        else
            CP_COMMIT();
        cp_wait<1>();      // stage kc's copies (this thread) have landed
        __syncthreads();   // make all threads' copies visible

        uint32_t sA  = sb + (kc & 1) * STAGEB;
        uint32_t sWh = sA + MATB, sWl = sA + 2 * MATB;
#pragma unroll
        for (int kk = 0; kk < 2; kk++) {
            uint32_t ah[4][4];
#pragma unroll
            for (int mt = 0; mt < 4; mt++)
                ldsm4(ah[mt], sA + aoff + mt * (16 * ROWB) + kk * 32);
            uint32_t bh[4][2], bl[4][2];
#pragma unroll
            for (int nt2 = 0; nt2 < 2; nt2++) {
                uint32_t r[4];
                ldsm4t(r, sWh + boff + nt2 * (16 * ROWB) + kk * 32);
                bh[nt2 * 2][0] = r[0]; bh[nt2 * 2][1] = r[1];
                bh[nt2 * 2 + 1][0] = r[2]; bh[nt2 * 2 + 1][1] = r[3];
                ldsm4t(r, sWl + boff + nt2 * (16 * ROWB) + kk * 32);
                bl[nt2 * 2][0] = r[0]; bl[nt2 * 2][1] = r[1];
                bl[nt2 * 2 + 1][0] = r[2]; bl[nt2 * 2 + 1][1] = r[3];
            }
#pragma unroll
            for (int mt = 0; mt < 4; mt++)
#pragma unroll
                for (int nt = 0; nt < 4; nt++) {
                    mma16816(acc[mt][nt], ah[mt], bh[nt]);
                    mma16816(acc[mt][nt], ah[mt], bl[nt]);
                }
        }
        __syncthreads();   // release stage kc before it is overwritten
    }

    // epilogue: add bias, store fp32
    int r0 = lane >> 2, c0 = (lane & 3) * 2;
#pragma unroll
    for (int nt = 0; nt < 4; nt++) {
        int col = j0 + nbase + nt * 8 + c0;
        float2 bb = *(const float2*)&b1[col];
#pragma unroll
        for (int mt = 0; mt < 4; mt++) {
            int row = m0 + mbase + mt * 16 + r0;
            float2 v0 = make_float2(acc[mt][nt][0] + bb.x, acc[mt][nt][1] + bb.y);
            float2 v1 = make_float2(acc[mt][nt][2] + bb.x, acc[mt][nt][3] + bb.y);
            *(float2*)&h1[(size_t)row * H1 + col]       = v0;
            *(float2*)&h1[(size_t)(row + 8) * H1 + col] = v1;
        }
    }
}

// ---------------------------------------------------------------------------
// Phase B: deterministic spike-sparse LIF stack.
// RB=8 rows/block (warp w owns row w for LIF1/LIF3), 256 blocks.
// ---------------------------------------------------------------------------
#define RB 8
__global__ __launch_bounds__(256) void phase_b_kernel(
    const float* __restrict__ h1all, const float* __restrict__ w2t,
    const float* __restrict__ b2,    const float* __restrict__ Wo,
    const float* __restrict__ bo,    float* __restrict__ out) {
    __shared__ short    idx1[RB][512];
    __shared__ int      cnt1[RB];
    __shared__ uint32_t s2bits[RB][8];
    __shared__ float    Wos[O_OUT * 256];
    __shared__ float    bos[8];

    int tid  = threadIdx.x;
    int wid  = tid >> 5, lane = tid & 31;
    int b0   = blockIdx.x * RB;

    for (int i = tid; i < O_OUT * 256; i += 256) Wos[i] = Wo[i];
    if (tid < O_OUT) bos[tid] = bo[tid];

    float v1[16];                       // LIF1: warp wid owns row wid, k=i*32+lane
#pragma unroll
    for (int i = 0; i < 16; i++) v1[i] = 0.0f;
    float v2[RB];                       // LIF2: thread owns col j=tid, all rows
#pragma unroll
    for (int r = 0; r < RB; r++) v2[r] = 0.0f;
    float b2r = b2[tid];
    float vo = 0.0f, oac = 0.0f;        // LIF3: warp wid = row, lanes 0..4 = cols
    __syncthreads();

#pragma unroll 1
    for (int t = 0; t < T_STEPS; t++) {
        // ---- LIF1 + deterministic fired-list (ballot compaction, asc k) ----
        const float* hrow = h1all + ((size_t)(b0 + wid) * T_STEPS + t) * H1;
        int base = 0;
#pragma unroll
        for (int i = 0; i < 16; i++) {
            float h = hrow[i * 32 + lane];
            float v = v1[i];
            v = v + (h - v) * 0.5f;
            bool sp = (v >= 1.0f);
            v1[i] = sp ? 0.0f : v;
            uint32_t m = __ballot_sync(0xffffffffu, sp);
            if (sp)
                idx1[wid][base + __popc(m & ((1u << lane) - 1u))] = (short)(i * 32 + lane);
            base += __popc(m);
        }
        if (lane == 0) cnt1[wid] = base;
        __syncthreads();

        // ---- sparse GEMM2 + LIF2 (thread = col j = tid) ----
#pragma unroll
        for (int r = 0; r < RB; r++) {
            float acc = b2r;
            int n = cnt1[r];
            for (int i = 0; i < n; i++)
                acc += w2t[(size_t)idx1[r][i] * H2 + tid];
            float v = v2[r];
            v = v + (acc - v) * 0.5f;
            bool sp = (v >= 1.0f);
            v2[r] = sp ? 0.0f : v;
            uint32_t m = __ballot_sync(0xffffffffu, sp);
            if (lane == (r & 31)) s2bits[r][wid] = m;
        }
        __syncthreads();

        // ---- sparse GEMM3 + LIF3 (warp wid = row, lanes 0..4 = outputs) ----
        if (lane < O_OUT) {
            float sum = bos[lane];
#pragma unroll
            for (int w = 0; w < 8; w++) {
                uint32_t word = s2bits[wid][w];
                while (word) {
                    int j = w * 32 + (__ffs(word) - 1);
                    word &= word - 1;
                    sum += Wos[lane * 256 + j];
                }
            }
            float v = vo;
            v = v + (sum - v) * 0.5f;
            bool sp = (v >= 1.0f);
            vo = sp ? 0.0f : v;
            if (sp) oac += 1.0f;
        }
        __syncthreads();   // lists/bits stable until here; next t overwrites
    }

    if (lane < O_OUT)
        out[(size_t)(b0 + wid) * O_OUT + lane] = oac * (1.0f / T_STEPS);
}

// ---------------------------------------------------------------------------
extern "C" void kernel_launch(void* const* d_in, const int* in_sizes, int n_in,
                              void* d_out, int out_size) {
    const float* x  = (const float*)d_in[0];
    const float* W1 = (const float*)d_in[1];
    const float* b1 = (const float*)d_in[2];
    const float* W2 = (const float*)d_in[3];
    const float* b2 = (const float*)d_in[4];
    const float* Wo = (const float*)d_in[5];
    const float* bo = (const float*)d_in[6];
    float* out = (float*)d_out;

    __half *xh, *wh, *wl;
    float *h1, *w2t;
    cudaGetSymbolAddress((void**)&xh,  g_xh);
    cudaGetSymbolAddress((void**)&wh,  g_w1h);
    cudaGetSymbolAddress((void**)&wl,  g_w1l);
    cudaGetSymbolAddress((void**)&h1,  g_h1);
    cudaGetSymbolAddress((void**)&w2t, g_w2t);

    cudaFuncSetAttribute(gemm1_mma_kernel,
                         cudaFuncAttributeMaxDynamicSharedMemorySize, GEMM_SMEM);

    transpose_half_x<<<dim3(4, 16, B_SZ), dim3(32, 8)>>>(x, xh);
    split_w1<<<(H1 * N_IN) / 256, 256>>>(W1, wh, wl);
    transpose_w2_kernel<<<dim3(16, 8), dim3(32, 8)>>>(W2, w2t);
    gemm1_mma_kernel<<<dim3(H1 / 128, M_TOT / 128), 256, GEMM_SMEM>>>(
        xh, wh, wl, b1, h1);
    phase_b_kernel<<<B_SZ / RB, 256>>>(h1, w2t, b2, Wo, bo, out);
}

// round 7
// speedup vs baseline: 7.7488x; 1.1669x over previous
#include <cuda_runtime.h>
#include <cuda_fp16.h>
#include <cstdint>

#define B_SZ    2048
#define N_IN    512
#define T_STEPS 100
#define H1      512
#define H2      256
#define O_OUT   5
#define M_TOT   (B_SZ * T_STEPS)   // 204800

// ---------------- scratch globals (allocation-free rule) ----------------
__device__ __half g_xh[(size_t)M_TOT * N_IN];   // x transposed, fp16
__device__ __half g_w1h[H1 * N_IN];             // W1 fp16
__device__ float  g_h1[(size_t)M_TOT * H1];     // fp32 h1 for all t
__device__ float  g_w2t[H1 * H2];               // W2 transposed [k][j]

// ---------------- PTX helpers ----------------
__device__ __forceinline__ uint32_t smem_u32(const void* p) {
    uint32_t a;
    asm("{ .reg .u64 t; cvta.to.shared.u64 t, %1; cvt.u32.u64 %0, t; }"
        : "=r"(a) : "l"(p));
    return a;
}
__device__ __forceinline__ void cp_async16(uint32_t dst, const void* src) {
    asm volatile("cp.async.cg.shared.global [%0], [%1], 16;" :: "r"(dst), "l"(src));
}
#define CP_COMMIT() asm volatile("cp.async.commit_group;" ::: "memory")
template <int N>
__device__ __forceinline__ void cp_wait() {
    asm volatile("cp.async.wait_group %0;" :: "n"(N) : "memory");
}
__device__ __forceinline__ void ldsm4(uint32_t* r, uint32_t addr) {
    asm volatile("ldmatrix.sync.aligned.m8n8.x4.shared.b16 {%0,%1,%2,%3}, [%4];"
                 : "=r"(r[0]), "=r"(r[1]), "=r"(r[2]), "=r"(r[3]) : "r"(addr));
}
__device__ __forceinline__ void ldsm4t(uint32_t* r, uint32_t addr) {
    asm volatile("ldmatrix.sync.aligned.m8n8.x4.trans.shared.b16 {%0,%1,%2,%3}, [%4];"
                 : "=r"(r[0]), "=r"(r[1]), "=r"(r[2]), "=r"(r[3]) : "r"(addr));
}
__device__ __forceinline__ void mma16816(float* c, const uint32_t* a, const uint32_t* b) {
    asm volatile("mma.sync.aligned.m16n8k16.row.col.f32.f16.f16.f32 "
                 "{%0,%1,%2,%3},{%4,%5,%6,%7},{%8,%9},{%0,%1,%2,%3};"
                 : "+f"(c[0]), "+f"(c[1]), "+f"(c[2]), "+f"(c[3])
                 : "r"(a[0]), "r"(a[1]), "r"(a[2]), "r"(a[3]), "r"(b[0]), "r"(b[1]));
}

// ---------------------------------------------------------------------------
// Transpose x (B, N, T) -> fp16 xh at [(b*T+t)][n]
// ---------------------------------------------------------------------------
__global__ void transpose_half_x(const float* __restrict__ x,
                                 __half* __restrict__ xh) {
    __shared__ float tile[32][33];
    int b  = blockIdx.z;
    int t0 = blockIdx.x * 32;
    int n0 = blockIdx.y * 32;
    int tx = threadIdx.x, ty = threadIdx.y;   // 32 x 8
#pragma unroll
    for (int i = 0; i < 4; i++) {
        int n = n0 + ty + i * 8;
        int t = t0 + tx;
        if (t < T_STEPS)
            tile[ty + i * 8][tx] = x[((size_t)b * N_IN + n) * T_STEPS + t];
    }
    __syncthreads();
#pragma unroll
    for (int i = 0; i < 4; i++) {
        int t = t0 + ty + i * 8;
        int n = n0 + tx;
        if (t < T_STEPS)
            xh[((size_t)b * T_STEPS + t) * N_IN + n] =
                __float2half_rn(tile[tx][ty + i * 8]);
    }
}

// ---------------------------------------------------------------------------
// Convert W1 to fp16
// ---------------------------------------------------------------------------
__global__ void conv_w1(const float* __restrict__ w, __half* __restrict__ wh) {
    int i = blockIdx.x * 256 + threadIdx.x;
    wh[i] = __float2half_rn(w[i]);
}

// ---------------------------------------------------------------------------
// Transpose W2 (H2, H1) -> (H1, H2)
// ---------------------------------------------------------------------------
__global__ void transpose_w2_kernel(const float* __restrict__ w2,
                                    float* __restrict__ w2t) {
    __shared__ float tile[32][33];
    int k0 = blockIdx.x * 32;
    int j0 = blockIdx.y * 32;
    int tx = threadIdx.x, ty = threadIdx.y;
#pragma unroll
    for (int i = 0; i < 4; i++)
        tile[ty + i * 8][tx] = w2[(size_t)(j0 + ty + i * 8) * H1 + k0 + tx];
    __syncthreads();
#pragma unroll
    for (int i = 0; i < 4; i++)
        w2t[(size_t)(k0 + ty + i * 8) * H2 + j0 + tx] = tile[tx][ty + i * 8];
}

// ---------------------------------------------------------------------------
// GEMM1 via mma.sync fp16, single pass:
//   h1[m][j] = sum_k x[m][k] * W1[j][k] + b1[j]
// BM=128, BN=128, BK=32, 3-stage cp.async pipeline, 2 CTAs/SM.
// Warp grid 2(m) x 4(n): per-warp 64x32 tile.
// ---------------------------------------------------------------------------
#define BK        32
#define NKC       (N_IN / BK)        // 16
#define ROWB      80                 // bytes per padded smem row (32h + 8h pad)
#define MATB      (128 * ROWB)       // 10240 bytes per matrix tile
#define STAGEB    (2 * MATB)         // A, W = 20480
#define GEMM_SMEM (3 * STAGEB)       // 61440

__device__ __forceinline__ void g1_load_stage(uint32_t sbase, int kc,
                                              const __half* xh, const __half* wh,
                                              int m0, int j0, int tid) {
    int kb = kc * BK;
#pragma unroll
    for (int i = 0; i < 2; i++) {
        int c = tid + i * 256;              // 0..511
        int row = c >> 2, seg = c & 3;
        uint32_t d = (uint32_t)(row * ROWB + seg * 16);
        cp_async16(sbase + d,        xh + (size_t)(m0 + row) * N_IN + kb + seg * 8);
        cp_async16(sbase + MATB + d, wh + (size_t)(j0 + row) * N_IN + kb + seg * 8);
    }
    CP_COMMIT();
}

__global__ __launch_bounds__(256, 2) void gemm1_mma_kernel(
    const __half* __restrict__ xh, const __half* __restrict__ wh,
    const float* __restrict__ b1, float* __restrict__ h1) {
    extern __shared__ char smem[];
    uint32_t sb = smem_u32(smem);
    int tid  = threadIdx.x;
    int wid  = tid >> 5, lane = tid & 31;
    int m0   = blockIdx.y * 128;
    int j0   = blockIdx.x * 128;
    int mbase = (wid & 1) * 64;          // 2 m-groups, warp tile 64 rows
    int nbase = (wid >> 1) * 32;         // 4 n-groups, warp tile 32 cols
    int grp  = lane >> 3, lrow = lane & 7;

    uint32_t aoff = (uint32_t)((mbase + (grp & 1) * 8 + lrow) * ROWB + (grp >> 1) * 16);
    uint32_t boff = (uint32_t)((nbase + (grp >> 1) * 8 + lrow) * ROWB + (grp & 1) * 16);

    float acc[4][4][4];
#pragma unroll
    for (int mt = 0; mt < 4; mt++)
#pragma unroll
        for (int nt = 0; nt < 4; nt++)
#pragma unroll
            for (int q = 0; q < 4; q++) acc[mt][nt][q] = 0.0f;

    // prologue: stages 0, 1
    g1_load_stage(sb,          0, xh, wh, m0, j0, tid);
    g1_load_stage(sb + STAGEB, 1, xh, wh, m0, j0, tid);

#pragma unroll 1
    for (int kc = 0; kc < NKC; kc++) {
        __syncthreads();   // all warps done with the buffer about to be refilled
        if (kc + 2 < NKC)
            g1_load_stage(sb + ((kc + 2) % 3) * STAGEB, kc + 2, xh, wh, m0, j0, tid);
        else
            CP_COMMIT();
        cp_wait<2>();      // stage kc's group has landed
        __syncthreads();

        uint32_t sA = sb + (kc % 3) * STAGEB;
        uint32_t sW = sA + MATB;
#pragma unroll
        for (int kk = 0; kk < 2; kk++) {
            uint32_t ah[4][4];
#pragma unroll
            for (int mt = 0; mt < 4; mt++)
                ldsm4(ah[mt], sA + aoff + mt * (16 * ROWB) + kk * 32);
            uint32_t bh[4][2];
#pragma unroll
            for (int nt2 = 0; nt2 < 2; nt2++) {
                uint32_t r[4];
                ldsm4t(r, sW + boff + nt2 * (16 * ROWB) + kk * 32);
                bh[nt2 * 2][0] = r[0]; bh[nt2 * 2][1] = r[1];
                bh[nt2 * 2 + 1][0] = r[2]; bh[nt2 * 2 + 1][1] = r[3];
            }
#pragma unroll
            for (int mt = 0; mt < 4; mt++)
#pragma unroll
                for (int nt = 0; nt < 4; nt++)
                    mma16816(acc[mt][nt], ah[mt], bh[nt]);
        }
    }

    // epilogue: add bias, store fp32
    int r0 = lane >> 2, c0 = (lane & 3) * 2;
#pragma unroll
    for (int nt = 0; nt < 4; nt++) {
        int col = j0 + nbase + nt * 8 + c0;
        float2 bb = *(const float2*)&b1[col];
#pragma unroll
        for (int mt = 0; mt < 4; mt++) {
            int row = m0 + mbase + mt * 16 + r0;
            float2 v0 = make_float2(acc[mt][nt][0] + bb.x, acc[mt][nt][1] + bb.y);
            float2 v1 = make_float2(acc[mt][nt][2] + bb.x, acc[mt][nt][3] + bb.y);
            *(float2*)&h1[(size_t)row * H1 + col]       = v0;
            *(float2*)&h1[(size_t)(row + 8) * H1 + col] = v1;
        }
    }
}

// ---------------------------------------------------------------------------
// Phase B: spike-sparse LIF stack, bitmask edition, prefetched h1.
// RB=4 rows/block, 512 blocks, 256 threads (8 warps).
// Warp w: row r = w>>1, k-half = (w&1)*256, 8 neurons/lane.
// Sparse sums iterate set bits in ascending k -> bitwise == dense ascending.
// ---------------------------------------------------------------------------
#define RB 4
__global__ __launch_bounds__(256) void phase_b_kernel(
    const float* __restrict__ h1all, const float* __restrict__ w2t,
    const float* __restrict__ b2,    const float* __restrict__ Wo,
    const float* __restrict__ bo,    float* __restrict__ out) {
    __shared__ uint32_t s1bits[RB][16];
    __shared__ uint32_t s2bits[RB][8];
    __shared__ float    Wos[O_OUT * 256];
    __shared__ float    bos[8];

    int tid  = threadIdx.x;
    int wid  = tid >> 5, lane = tid & 31;
    int b0   = blockIdx.x * RB;
    int row  = wid >> 1;                 // 0..3
    int half = wid & 1;                  // k-half

    for (int i = tid; i < O_OUT * 256; i += 256) Wos[i] = Wo[i];
    if (tid < O_OUT) bos[tid] = bo[tid];

    float v1[8];
#pragma unroll
    for (int i = 0; i < 8; i++) v1[i] = 0.0f;
    float v2[RB];
#pragma unroll
    for (int r = 0; r < RB; r++) v2[r] = 0.0f;
    float b2r = b2[tid];
    float vo = 0.0f, oac = 0.0f;         // LIF3: warp<4 = row, lanes 0..4 = cols

    const float* hbase = h1all + ((size_t)(b0 + row) * T_STEPS) * H1
                               + half * 256 + lane;
    // prefetch t=0
    float cur[8], nxt[8];
#pragma unroll
    for (int i = 0; i < 8; i++) cur[i] = hbase[i * 32];
    __syncthreads();

#pragma unroll 1
    for (int t = 0; t < T_STEPS; t++) {
        // issue next-t loads early (independent of everything below)
        if (t + 1 < T_STEPS) {
            const float* hn = hbase + (size_t)(t + 1) * H1;
#pragma unroll
            for (int i = 0; i < 8; i++) nxt[i] = hn[i * 32];
        }

        // ---- LIF1 -> bitmask ----
#pragma unroll
        for (int i = 0; i < 8; i++) {
            float v = v1[i];
            v = v + (cur[i] - v) * 0.5f;
            bool sp = (v >= 1.0f);
            v1[i] = sp ? 0.0f : v;
            uint32_t m = __ballot_sync(0xffffffffu, sp);
            if (lane == 0) s1bits[row][half * 8 + i] = m;
        }
        __syncthreads();

        // ---- sparse GEMM2 + LIF2 (thread = col j = tid) ----
#pragma unroll
        for (int r = 0; r < RB; r++) {
            float acc = b2r;
#pragma unroll
            for (int w = 0; w < 16; w++) {
                uint32_t word = s1bits[r][w];
                while (word) {
                    int k = w * 32 + (__ffs(word) - 1);
                    word &= word - 1;
                    acc += w2t[(size_t)k * H2 + tid];
                }
            }
            float v = v2[r];
            v = v + (acc - v) * 0.5f;
            bool sp = (v >= 1.0f);
            v2[r] = sp ? 0.0f : v;
            uint32_t m = __ballot_sync(0xffffffffu, sp);
            if (lane == 0) s2bits[r][wid] = m;
        }
        __syncthreads();

        // ---- sparse GEMM3 + LIF3 (warp<4 = row, lanes 0..4 = outputs) ----
        if (wid < RB && lane < O_OUT) {
            float sum = bos[lane];
#pragma unroll
            for (int w = 0; w < 8; w++) {
                uint32_t word = s2bits[wid][w];
                while (word) {
                    int j = w * 32 + (__ffs(word) - 1);
                    word &= word - 1;
                    sum += Wos[lane * 256 + j];
                }
            }
            float v = vo;
            v = v + (sum - v) * 0.5f;
            bool sp = (v >= 1.0f);
            vo = sp ? 0.0f : v;
            if (sp) oac += 1.0f;
        }
        __syncthreads();   // bits stable until here; next t overwrites

#pragma unroll
        for (int i = 0; i < 8; i++) cur[i] = nxt[i];
    }

    if (wid < RB && lane < O_OUT)
        out[(size_t)(b0 + wid) * O_OUT + lane] = oac * (1.0f / T_STEPS);
}

// ---------------------------------------------------------------------------
extern "C" void kernel_launch(void* const* d_in, const int* in_sizes, int n_in,
                              void* d_out, int out_size) {
    const float* x  = (const float*)d_in[0];
    const float* W1 = (const float*)d_in[1];
    const float* b1 = (const float*)d_in[2];
    const float* W2 = (const float*)d_in[3];
    const float* b2 = (const float*)d_in[4];
    const float* Wo = (const float*)d_in[5];
    const float* bo = (const float*)d_in[6];
    float* out = (float*)d_out;

    __half *xh, *wh;
    float *h1, *w2t;
    cudaGetSymbolAddress((void**)&xh,  g_xh);
    cudaGetSymbolAddress((void**)&wh,  g_w1h);
    cudaGetSymbolAddress((void**)&h1,  g_h1);
    cudaGetSymbolAddress((void**)&w2t, g_w2t);

    cudaFuncSetAttribute(gemm1_mma_kernel,
                         cudaFuncAttributeMaxDynamicSharedMemorySize, GEMM_SMEM);

    transpose_half_x<<<dim3(4, 16, B_SZ), dim3(32, 8)>>>(x, xh);
    conv_w1<<<(H1 * N_IN) / 256, 256>>>(W1, wh);
    transpose_w2_kernel<<<dim3(16, 8), dim3(32, 8)>>>(W2, w2t);
    gemm1_mma_kernel<<<dim3(H1 / 128, M_TOT / 128), 256, GEMM_SMEM>>>(
        xh, wh, b1, h1);
    phase_b_kernel<<<B_SZ / RB, 256>>>(h1, w2t, b2, Wo, bo, out);
}

// round 9
// speedup vs baseline: 9.2819x; 1.1979x over previous
#include <cuda_runtime.h>
#include <cuda_fp16.h>
#include <cstdint>

#define B_SZ    2048
#define N_IN    512
#define T_STEPS 100
#define H1      512
#define H2      256
#define O_OUT   5
#define M_TOT   (B_SZ * T_STEPS)   // 204800

// ---------------- scratch globals (allocation-free rule) ----------------
__device__ __half g_xh[(size_t)M_TOT * N_IN];   // x transposed, fp16
__device__ __half g_w1h[H1 * N_IN];             // W1 fp16
__device__ __half g_h1[(size_t)M_TOT * H1];     // fp16 h1 for all t
__device__ float  g_w2t[H1 * H2];               // W2 transposed [k][j]

// ---------------- PTX helpers ----------------
__device__ __forceinline__ uint32_t smem_u32(const void* p) {
    uint32_t a;
    asm("{ .reg .u64 t; cvta.to.shared.u64 t, %1; cvt.u32.u64 %0, t; }"
        : "=r"(a) : "l"(p));
    return a;
}
__device__ __forceinline__ void cp_async16(uint32_t dst, const void* src) {
    asm volatile("cp.async.cg.shared.global [%0], [%1], 16;" :: "r"(dst), "l"(src));
}
#define CP_COMMIT() asm volatile("cp.async.commit_group;" ::: "memory")
template <int N>
__device__ __forceinline__ void cp_wait() {
    asm volatile("cp.async.wait_group %0;" :: "n"(N) : "memory");
}
__device__ __forceinline__ void ldsm4(uint32_t* r, uint32_t addr) {
    asm volatile("ldmatrix.sync.aligned.m8n8.x4.shared.b16 {%0,%1,%2,%3}, [%4];"
                 : "=r"(r[0]), "=r"(r[1]), "=r"(r[2]), "=r"(r[3]) : "r"(addr));
}
__device__ __forceinline__ void ldsm4t(uint32_t* r, uint32_t addr) {
    asm volatile("ldmatrix.sync.aligned.m8n8.x4.trans.shared.b16 {%0,%1,%2,%3}, [%4];"
                 : "=r"(r[0]), "=r"(r[1]), "=r"(r[2]), "=r"(r[3]) : "r"(addr));
}
__device__ __forceinline__ void mma16816(float* c, const uint32_t* a, const uint32_t* b) {
    asm volatile("mma.sync.aligned.m16n8k16.row.col.f32.f16.f16.f32 "
                 "{%0,%1,%2,%3},{%4,%5,%6,%7},{%8,%9},{%0,%1,%2,%3};"
                 : "+f"(c[0]), "+f"(c[1]), "+f"(c[2]), "+f"(c[3])
                 : "r"(a[0]), "r"(a[1]), "r"(a[2]), "r"(a[3]), "r"(b[0]), "r"(b[1]));
}

// ---------------------------------------------------------------------------
// Transpose x (B, N, T) -> fp16 xh at [(b*T+t)][n]
// ---------------------------------------------------------------------------
__global__ void transpose_half_x(const float* __restrict__ x,
                                 __half* __restrict__ xh) {
    __shared__ float tile[32][33];
    int b  = blockIdx.z;
    int t0 = blockIdx.x * 32;
    int n0 = blockIdx.y * 32;
    int tx = threadIdx.x, ty = threadIdx.y;   // 32 x 8
#pragma unroll
    for (int i = 0; i < 4; i++) {
        int n = n0 + ty + i * 8;
        int t = t0 + tx;
        if (t < T_STEPS)
            tile[ty + i * 8][tx] = x[((size_t)b * N_IN + n) * T_STEPS + t];
    }
    __syncthreads();
#pragma unroll
    for (int i = 0; i < 4; i++) {
        int t = t0 + ty + i * 8;
        int n = n0 + tx;
        if (t < T_STEPS)
            xh[((size_t)b * T_STEPS + t) * N_IN + n] =
                __float2half_rn(tile[tx][ty + i * 8]);
    }
}

// ---------------------------------------------------------------------------
// Convert W1 to fp16
// ---------------------------------------------------------------------------
__global__ void conv_w1(const float* __restrict__ w, __half* __restrict__ wh) {
    int i = blockIdx.x * 256 + threadIdx.x;
    wh[i] = __float2half_rn(w[i]);
}

// ---------------------------------------------------------------------------
// Transpose W2 (H2, H1) -> (H1, H2)
// ---------------------------------------------------------------------------
__global__ void transpose_w2_kernel(const float* __restrict__ w2,
                                    float* __restrict__ w2t) {
    __shared__ float tile[32][33];
    int k0 = blockIdx.x * 32;
    int j0 = blockIdx.y * 32;
    int tx = threadIdx.x, ty = threadIdx.y;
#pragma unroll
    for (int i = 0; i < 4; i++)
        tile[ty + i * 8][tx] = w2[(size_t)(j0 + ty + i * 8) * H1 + k0 + tx];
    __syncthreads();
#pragma unroll
    for (int i = 0; i < 4; i++)
        w2t[(size_t)(k0 + ty + i * 8) * H2 + j0 + tx] = tile[tx][ty + i * 8];
}

// ---------------------------------------------------------------------------
// GEMM1 via mma.sync fp16, single pass, fp16 output:
//   h1[m][j] = fp16( sum_k x[m][k] * W1[j][k] + b1[j] )
// BM=128, BN=128, BK=32, 4-stage cp.async pipeline, 2 CTAs/SM.
// ---------------------------------------------------------------------------
#define BK        32
#define NKC       (N_IN / BK)        // 16
#define ROWB      80                 // bytes per padded smem row (32h + 8h pad)
#define MATB      (128 * ROWB)       // 10240 bytes per matrix tile
#define STAGEB    (2 * MATB)         // A, W = 20480
#define NSTAGE    4
#define GEMM_SMEM (NSTAGE * STAGEB)  // 81920

__device__ __forceinline__ void g1_load_stage(uint32_t sbase, int kc,
                                              const __half* xh, const __half* wh,
                                              int m0, int j0, int tid) {
    int kb = kc * BK;
#pragma unroll
    for (int i = 0; i < 2; i++) {
        int c = tid + i * 256;              // 0..511
        int row = c >> 2, seg = c & 3;
        uint32_t d = (uint32_t)(row * ROWB + seg * 16);
        cp_async16(sbase + d,        xh + (size_t)(m0 + row) * N_IN + kb + seg * 8);
        cp_async16(sbase + MATB + d, wh + (size_t)(j0 + row) * N_IN + kb + seg * 8);
    }
    CP_COMMIT();
}

__global__ __launch_bounds__(256, 2) void gemm1_mma_kernel(
    const __half* __restrict__ xh, const __half* __restrict__ wh,
    const float* __restrict__ b1, __half* __restrict__ h1) {
    extern __shared__ char smem[];
    uint32_t sb = smem_u32(smem);
    int tid  = threadIdx.x;
    int wid  = tid >> 5, lane = tid & 31;
    int m0   = blockIdx.y * 128;
    int j0   = blockIdx.x * 128;
    int mbase = (wid & 1) * 64;          // 2 m-groups, warp tile 64 rows
    int nbase = (wid >> 1) * 32;         // 4 n-groups, warp tile 32 cols
    int grp  = lane >> 3, lrow = lane & 7;

    uint32_t aoff = (uint32_t)((mbase + (grp & 1) * 8 + lrow) * ROWB + (grp >> 1) * 16);
    uint32_t boff = (uint32_t)((nbase + (grp >> 1) * 8 + lrow) * ROWB + (grp & 1) * 16);

    float acc[4][4][4];
#pragma unroll
    for (int mt = 0; mt < 4; mt++)
#pragma unroll
        for (int nt = 0; nt < 4; nt++)
#pragma unroll
            for (int q = 0; q < 4; q++) acc[mt][nt][q] = 0.0f;

    // prologue: stages 0..2
    g1_load_stage(sb,              0, xh, wh, m0, j0, tid);
    g1_load_stage(sb + STAGEB,     1, xh, wh, m0, j0, tid);
    g1_load_stage(sb + 2 * STAGEB, 2, xh, wh, m0, j0, tid);

#pragma unroll 1
    for (int kc = 0; kc < NKC; kc++) {
        __syncthreads();   // all warps done with the buffer about to be refilled
        if (kc + 3 < NKC)
            g1_load_stage(sb + ((kc + 3) % NSTAGE) * STAGEB, kc + 3,
                          xh, wh, m0, j0, tid);
        else
            CP_COMMIT();
        cp_wait<3>();      // stage kc's group has landed
        __syncthreads();

        uint32_t sA = sb + (kc % NSTAGE) * STAGEB;
        uint32_t sW = sA + MATB;
#pragma unroll
        for (int kk = 0; kk < 2; kk++) {
            uint32_t ah[4][4];
#pragma unroll
            for (int mt = 0; mt < 4; mt++)
                ldsm4(ah[mt], sA + aoff + mt * (16 * ROWB) + kk * 32);
            uint32_t bh[4][2];
#pragma unroll
            for (int nt2 = 0; nt2 < 2; nt2++) {
                uint32_t r[4];
                ldsm4t(r, sW + boff + nt2 * (16 * ROWB) + kk * 32);
                bh[nt2 * 2][0] = r[0]; bh[nt2 * 2][1] = r[1];
                bh[nt2 * 2 + 1][0] = r[2]; bh[nt2 * 2 + 1][1] = r[3];
            }
#pragma unroll
            for (int mt = 0; mt < 4; mt++)
#pragma unroll
                for (int nt = 0; nt < 4; nt++)
                    mma16816(acc[mt][nt], ah[mt], bh[nt]);
        }
    }

    // epilogue: add bias, store fp16
    int r0 = lane >> 2, c0 = (lane & 3) * 2;
#pragma unroll
    for (int nt = 0; nt < 4; nt++) {
        int col = j0 + nbase + nt * 8 + c0;
        float2 bb = *(const float2*)&b1[col];
#pragma unroll
        for (int mt = 0; mt < 4; mt++) {
            int row = m0 + mbase + mt * 16 + r0;
            __half2 v0 = __floats2half2_rn(acc[mt][nt][0] + bb.x, acc[mt][nt][1] + bb.y);
            __half2 v1 = __floats2half2_rn(acc[mt][nt][2] + bb.x, acc[mt][nt][3] + bb.y);
            *(__half2*)&h1[(size_t)row * H1 + col]       = v0;
            *(__half2*)&h1[(size_t)(row + 8) * H1 + col] = v1;
        }
    }
}

// ---------------------------------------------------------------------------
// Phase B: spike-sparse LIF stack. RB=2 rows/block, 1024 blocks, 256 threads.
// Warp w: row = w>>2, quarter q = w&3, neurons k = q*128 + i*32 + lane (i<4).
// Double-buffered bitmasks -> 2 barriers/step. uint4 zero-skip word scan.
// ---------------------------------------------------------------------------
#define RB 2
__global__ __launch_bounds__(256) void phase_b_kernel(
    const __half* __restrict__ h1all, const float* __restrict__ w2t,
    const float* __restrict__ b2,    const float* __restrict__ Wo,
    const float* __restrict__ bo,    float* __restrict__ out) {
    __shared__ uint32_t s1bits[2][RB][16];
    __shared__ uint32_t s2bits[2][RB][8];
    __shared__ float    Wos[O_OUT * 256];
    __shared__ float    bos[8];

    int tid  = threadIdx.x;
    int wid  = tid >> 5, lane = tid & 31;
    int b0   = blockIdx.x * RB;
    int row  = wid >> 2;                 // 0..1
    int quar = wid & 3;                  // k-quarter

    for (int i = tid; i < O_OUT * 256; i += 256) Wos[i] = Wo[i];
    if (tid < O_OUT) bos[tid] = bo[tid];

    float v1[4];
#pragma unroll
    for (int i = 0; i < 4; i++) v1[i] = 0.0f;
    float v2[RB];
#pragma unroll
    for (int r = 0; r < RB; r++) v2[r] = 0.0f;
    float b2r = b2[tid];
    float vo = 0.0f, oac = 0.0f;         // LIF3: wid<2 = row, lanes 0..4 = cols

    const __half* hbase = h1all + ((size_t)(b0 + row) * T_STEPS) * H1
                                + quar * 128 + lane;
    // prefetch t=0
    __half cur[4], nxt[4];
#pragma unroll
    for (int i = 0; i < 4; i++) cur[i] = hbase[i * 32];
    __syncthreads();

#pragma unroll 1
    for (int t = 0; t < T_STEPS; t++) {
        int buf = t & 1;
        // issue next-t loads early (independent of everything below)
        if (t + 1 < T_STEPS) {
            const __half* hn = hbase + (size_t)(t + 1) * H1;
#pragma unroll
            for (int i = 0; i < 4; i++) nxt[i] = hn[i * 32];
        }

        // ---- LIF1 -> bitmask (word = quar*4+i, bit = lane) ----
#pragma unroll
        for (int i = 0; i < 4; i++) {
            float v = v1[i];
            v = v + (__half2float(cur[i]) - v) * 0.5f;
            bool sp = (v >= 1.0f);
            v1[i] = sp ? 0.0f : v;
            uint32_t m = __ballot_sync(0xffffffffu, sp);
            if (lane == 0) s1bits[buf][row][quar * 4 + i] = m;
        }
        __syncthreads();

        // ---- sparse GEMM2 + LIF2 (thread = col j = tid) ----
#pragma unroll
        for (int r = 0; r < RB; r++) {
            float acc = b2r;
            const uint4* wq = (const uint4*)s1bits[buf][r];
#pragma unroll
            for (int q = 0; q < 4; q++) {
                uint4 w4 = wq[q];
                if ((w4.x | w4.y | w4.z | w4.w) == 0u) continue;
                uint32_t ws[4] = {w4.x, w4.y, w4.z, w4.w};
#pragma unroll
                for (int c = 0; c < 4; c++) {
                    uint32_t word = ws[c];
                    while (word) {
                        int k = (q * 4 + c) * 32 + (__ffs(word) - 1);
                        word &= word - 1;
                        acc += w2t[(size_t)k * H2 + tid];
                    }
                }
            }
            float v = v2[r];
            v = v + (acc - v) * 0.5f;
            bool sp = (v >= 1.0f);
            v2[r] = sp ? 0.0f : v;
            uint32_t m = __ballot_sync(0xffffffffu, sp);
            if (lane == 0) s2bits[buf][r][wid] = m;
        }
        __syncthreads();

        // ---- sparse GEMM3 + LIF3 (wid<2 = row, lanes 0..4 = outputs) ----
        if (wid < RB && lane < O_OUT) {
            float sum = bos[lane];
#pragma unroll
            for (int w = 0; w < 8; w++) {
                uint32_t word = s2bits[buf][wid][w];
                while (word) {
                    int j = w * 32 + (__ffs(word) - 1);
                    word &= word - 1;
                    sum += Wos[lane * 256 + j];
                }
            }
            float v = vo;
            v = v + (sum - v) * 0.5f;
            bool sp = (v >= 1.0f);
            vo = sp ? 0.0f : v;
            if (sp) oac += 1.0f;
        }
        // no barrier: next step writes the OTHER buffer

#pragma unroll
        for (int i = 0; i < 4; i++) cur[i] = nxt[i];
    }

    if (wid < RB && lane < O_OUT)
        out[(size_t)(b0 + wid) * O_OUT + lane] = oac * (1.0f / T_STEPS);
}

// ---------------------------------------------------------------------------
extern "C" void kernel_launch(void* const* d_in, const int* in_sizes, int n_in,
                              void* d_out, int out_size) {
    const float* x  = (const float*)d_in[0];
    const float* W1 = (const float*)d_in[1];
    const float* b1 = (const float*)d_in[2];
    const float* W2 = (const float*)d_in[3];
    const float* b2 = (const float*)d_in[4];
    const float* Wo = (const float*)d_in[5];
    const float* bo = (const float*)d_in[6];
    float* out = (float*)d_out;

    __half *xh, *wh, *h1;
    float *w2t;
    cudaGetSymbolAddress((void**)&xh,  g_xh);
    cudaGetSymbolAddress((void**)&wh,  g_w1h);
    cudaGetSymbolAddress((void**)&h1,  g_h1);
    cudaGetSymbolAddress((void**)&w2t, g_w2t);

    cudaFuncSetAttribute(gemm1_mma_kernel,
                         cudaFuncAttributeMaxDynamicSharedMemorySize, GEMM_SMEM);

    transpose_half_x<<<dim3(4, 16, B_SZ), dim3(32, 8)>>>(x, xh);
    conv_w1<<<(H1 * N_IN) / 256, 256>>>(W1, wh);
    transpose_w2_kernel<<<dim3(16, 8), dim3(32, 8)>>>(W2, w2t);
    gemm1_mma_kernel<<<dim3(H1 / 128, M_TOT / 128), 256, GEMM_SMEM>>>(
        xh, wh, b1, h1);
    phase_b_kernel<<<B_SZ / RB, 256>>>(h1, w2t, b2, Wo, bo, out);
}